// round 14
// baseline (speedup 1.0000x reference)
#include <cuda_runtime.h>
#include <cuda_fp16.h>
#include <cuda_bf16.h>
#include <math_constants.h>

// ---------------- problem constants ----------------
#define N_NODES 100000
#define N_EDGES 1600000
#define DIM_IN  128
#define DIM_HID 128
#define DIM_OUT 64
#define NEG_SLOPE 0.2f

#define KDIM 128
#define NKS  (KDIM / 16)              // 8 k-steps of 16
#define PAD_TILES 6256                // covers 782*8 (gemm1) and 391*16 (gemm2)
#define REAL_TILES (N_NODES / 16)     // 6250 exactly

#define SCAN_BLK 1024
#define N_SCAN_BLOCKS ((N_NODES + SCAN_BLK - 1) / SCAN_BLK)   // 98

// ---------------- scratch (device globals; no allocation allowed) ----------
__device__ __half g_h1[(size_t)N_NODES * DIM_HID];
__device__ __half g_h2[(size_t)N_NODES * DIM_OUT];
__device__ float  g_asrc[N_NODES],  g_adst[N_NODES];
__device__ float  g_asrc2[N_NODES], g_adst2[N_NODES];
__device__ float  g_p1[2 * 128];
__device__ float  g_p2[2 * 128];

__device__ unsigned g_AfH[(size_t)PAD_TILES * NKS * 32 * 4];
__device__ unsigned g_AfL[(size_t)PAD_TILES * NKS * 32 * 4];
__device__ unsigned g_WfH1[16 * NKS * 32 * 2], g_WfL1[16 * NKS * 32 * 2];
__device__ unsigned g_WfH2[8  * NKS * 32 * 2], g_WfL2[8  * NKS * 32 * 2];

// CSR scratch
__device__ int g_cnt[N_NODES];
__device__ int g_incl[N_NODES];
__device__ int g_bsum[N_SCAN_BLOCKS];
__device__ int g_boff[N_SCAN_BLOCKS];
__device__ int g_rowptr[N_NODES + 1];
__device__ int g_woff[N_NODES];
__device__ int g_csr_src[N_EDGES];

// ---------------- CSR build ----------------
__global__ void hist_kernel(const int* __restrict__ dst) {
    int e = blockIdx.x * blockDim.x + threadIdx.x;
    if (e >= N_EDGES) return;
    int d = dst[e];
    if ((unsigned)d < N_NODES) atomicAdd(&g_cnt[d], 1);
}

__global__ void scan1_kernel() {
    __shared__ int wsum[32];
    int tid  = threadIdx.x;
    int lane = tid & 31;
    int wid  = tid >> 5;
    int i = blockIdx.x * SCAN_BLK + tid;
    int x = (i < N_NODES) ? g_cnt[i] : 0;
    #pragma unroll
    for (int off = 1; off < 32; off <<= 1) {
        int y = __shfl_up_sync(0xffffffffu, x, off);
        if (lane >= off) x += y;
    }
    if (lane == 31) wsum[wid] = x;
    __syncthreads();
    if (wid == 0) {
        int y = wsum[lane];
        #pragma unroll
        for (int off = 1; off < 32; off <<= 1) {
            int z = __shfl_up_sync(0xffffffffu, y, off);
            if (lane >= off) y += z;
        }
        wsum[lane] = y;
    }
    __syncthreads();
    if (wid > 0) x += wsum[wid - 1];
    if (i < N_NODES) g_incl[i] = x;
    if (tid == SCAN_BLK - 1) g_bsum[blockIdx.x] = x;
}

__global__ void scan2_kernel() {
    __shared__ int s[128];
    int tid = threadIdx.x;
    int v0 = (tid < N_SCAN_BLOCKS) ? g_bsum[tid] : 0;
    s[tid] = v0;
    __syncthreads();
    #pragma unroll
    for (int off = 1; off < 128; off <<= 1) {
        int v = (tid >= off) ? s[tid - off] : 0;
        __syncthreads();
        s[tid] += v;
        __syncthreads();
    }
    if (tid < N_SCAN_BLOCKS) g_boff[tid] = s[tid] - v0;
}

__global__ void scan3_kernel() {
    int i = blockIdx.x * blockDim.x + threadIdx.x;
    if (i >= N_NODES) return;
    int excl = g_incl[i] - g_cnt[i] + g_boff[i / SCAN_BLK];
    g_rowptr[i] = excl;
    g_woff[i]   = excl;
    if (i == 0) g_rowptr[N_NODES] = N_EDGES;
}

__global__ void scatter_kernel(const int* __restrict__ src, const int* __restrict__ dst) {
    int e = blockIdx.x * blockDim.x + threadIdx.x;
    if (e >= N_EDGES) return;
    int s = src[e];
    int d = dst[e];
    if ((unsigned)s >= N_NODES || (unsigned)d >= N_NODES) return;
    int pos = atomicAdd(&g_woff[d], 1);
    g_csr_src[pos] = s;
}

// ---------------- bf16 split / pack helpers ----------------
__device__ __forceinline__ void split_bf16(float x, __nv_bfloat16& h, __nv_bfloat16& l) {
    h = __float2bfloat16_rn(x);
    l = __float2bfloat16_rn(x - __bfloat162float(h));
}
__device__ __forceinline__ unsigned pack_bf16(__nv_bfloat16 a, __nv_bfloat16 b) {
    __nv_bfloat162 t;
    t.x = a; t.y = b;
    return *(unsigned*)&t;
}
__device__ __forceinline__ void pack_hl(float x, float y, unsigned& hw, unsigned& lw) {
    __nv_bfloat16 hx, lx, hy, ly;
    split_bf16(x, hx, lx);
    split_bf16(y, hy, ly);
    hw = pack_bf16(hx, hy);
    lw = pack_bf16(lx, ly);
}

// ---------------- merged prep: p1, p2, W1 frags, W2 frags in one launch -----
__device__ __forceinline__ void convertW_body(const float* __restrict__ W, int COUT, int ct,
                                              unsigned* __restrict__ WfH,
                                              unsigned* __restrict__ WfL) {
    int ks   = threadIdx.x >> 5;
    int lane = threadIdx.x & 31;
    int g = lane >> 2, t = lane & 3;
    size_t base = (((size_t)ct * NKS + ks) * 32 + lane) * 2;
    #pragma unroll
    for (int r = 0; r < 2; r++) {
        int k   = ks * 16 + 2 * t + r * 8;
        int col = ct * 8 + g;
        float e0 = W[(size_t)k * COUT + col];
        float e1 = W[(size_t)(k + 1) * COUT + col];
        __nv_bfloat16 h0, l0, h1, l1;
        split_bf16(e0, h0, l0);
        split_bf16(e1, h1, l1);
        WfH[base + r] = pack_bf16(h0, h1);
        WfL[base + r] = pack_bf16(l0, l1);
    }
}

__global__ void prep_all_kernel(const float* __restrict__ W1s, const float* __restrict__ a1s,
                                const float* __restrict__ W1d, const float* __restrict__ a1d,
                                const float* __restrict__ W2s, const float* __restrict__ a2s,
                                const float* __restrict__ W2d, const float* __restrict__ a2d) {
    int b = blockIdx.x;
    if (b == 0) {
        if (threadIdx.x >= 128) return;
        int i = threadIdx.x;
        float s = 0.f, d = 0.f;
        for (int c = 0; c < DIM_HID; c++) {
            s += W1s[i * DIM_HID + c] * a1s[c];
            d += W1d[i * DIM_HID + c] * a1d[c];
        }
        g_p1[i] = s;
        g_p1[128 + i] = d;
    } else if (b == 1) {
        if (threadIdx.x >= 128) return;
        int i = threadIdx.x;
        float s = 0.f, d = 0.f;
        for (int c = 0; c < DIM_OUT; c++) {
            s += W2s[i * DIM_OUT + c] * a2s[c];
            d += W2d[i * DIM_OUT + c] * a2d[c];
        }
        g_p2[i] = s;
        g_p2[128 + i] = d;
    } else if (b < 2 + DIM_HID / 8) {
        convertW_body(W1s, DIM_HID, b - 2, g_WfH1, g_WfL1);
    } else {
        convertW_body(W2s, DIM_OUT, b - 2 - DIM_HID / 8, g_WfH2, g_WfL2);
    }
}

// ---------------- row_prep: tile per block, warp owns row-pair (w, w+8) ----
__global__ __launch_bounds__(256)
void row_prep_kernel(const float* __restrict__ feat) {
    __shared__ unsigned sH[8][2][64];
    __shared__ unsigned sL[8][2][64];
    int tile = blockIdx.x;
    int wid  = threadIdx.x >> 5;
    int lane = threadIdx.x & 31;

    float4 ps = ((const float4*)g_p1)[lane];
    float4 pd = ((const float4*)(g_p1 + 128))[lane];
    int r0 = tile * 16 + wid;
    int r1 = r0 + 8;
    float4 v0 = make_float4(0.f, 0.f, 0.f, 0.f);
    float4 v1 = make_float4(0.f, 0.f, 0.f, 0.f);
    if (r0 < N_NODES) v0 = ((const float4*)(feat + (size_t)r0 * 128))[lane];
    if (r1 < N_NODES) v1 = ((const float4*)(feat + (size_t)r1 * 128))[lane];

    float s0 = v0.x * ps.x + v0.y * ps.y + v0.z * ps.z + v0.w * ps.w;
    float d0 = v0.x * pd.x + v0.y * pd.y + v0.z * pd.z + v0.w * pd.w;
    float s1 = v1.x * ps.x + v1.y * ps.y + v1.z * ps.z + v1.w * ps.w;
    float d1 = v1.x * pd.x + v1.y * pd.y + v1.z * pd.z + v1.w * pd.w;
    #pragma unroll
    for (int o = 16; o > 0; o >>= 1) {
        s0 += __shfl_xor_sync(0xffffffffu, s0, o);
        d0 += __shfl_xor_sync(0xffffffffu, d0, o);
        s1 += __shfl_xor_sync(0xffffffffu, s1, o);
        d1 += __shfl_xor_sync(0xffffffffu, d1, o);
    }
    if (lane == 0) {
        if (r0 < N_NODES) { g_asrc[r0] = s0; g_adst[r0] = d0; }
        if (r1 < N_NODES) { g_asrc[r1] = s1; g_adst[r1] = d1; }
    }

    unsigned hw, lw;
    pack_hl(v0.x, v0.y, hw, lw); sH[wid][0][2 * lane] = hw;     sL[wid][0][2 * lane] = lw;
    pack_hl(v0.z, v0.w, hw, lw); sH[wid][0][2 * lane + 1] = hw; sL[wid][0][2 * lane + 1] = lw;
    pack_hl(v1.x, v1.y, hw, lw); sH[wid][1][2 * lane] = hw;     sL[wid][1][2 * lane] = lw;
    pack_hl(v1.z, v1.w, hw, lw); sH[wid][1][2 * lane + 1] = hw; sL[wid][1][2 * lane + 1] = lw;
    __syncwarp();

    int ks = lane >> 2, tt = lane & 3;
    uint4 H4, L4;
    H4.x = sH[wid][0][8 * ks + tt];     H4.y = sH[wid][1][8 * ks + tt];
    H4.z = sH[wid][0][8 * ks + 4 + tt]; H4.w = sH[wid][1][8 * ks + 4 + tt];
    L4.x = sL[wid][0][8 * ks + tt];     L4.y = sL[wid][1][8 * ks + tt];
    L4.z = sL[wid][0][8 * ks + 4 + tt]; L4.w = sL[wid][1][8 * ks + 4 + tt];
    size_t a = ((size_t)(tile * 8 + ks)) * 32 + 4 * wid + tt;
    ((uint4*)g_AfH)[a] = H4;
    ((uint4*)g_AfL)[a] = L4;
}

// ---------------- bf16 3x mma GEMM (uint4 A frags) --------------
__device__ __forceinline__ void mma_bf16(float c[4], const unsigned a[4], const unsigned b[2]) {
    asm volatile(
        "mma.sync.aligned.m16n8k16.row.col.f32.bf16.bf16.f32 "
        "{%0,%1,%2,%3}, {%4,%5,%6,%7}, {%8,%9}, {%0,%1,%2,%3};"
        : "+f"(c[0]), "+f"(c[1]), "+f"(c[2]), "+f"(c[3])
        : "r"(a[0]), "r"(a[1]), "r"(a[2]), "r"(a[3]), "r"(b[0]), "r"(b[1]));
}

template<int COUT>
__global__ __launch_bounds__(256, 2)
void gemm_frag_kernel(__half* __restrict__ H, int nrows,
                      const unsigned* __restrict__ WfHp, const unsigned* __restrict__ WfLp) {
    constexpr int WN = (COUT == 128) ? 2 : 1;
    constexpr int WMCNT = 8 / WN;
    constexpr int ROWS = WMCNT * 32;

    int wid  = threadIdx.x >> 5;
    int lane = threadIdx.x & 31;
    int g = lane >> 2, t = lane & 3;
    int warp_m = (COUT == 128) ? (wid >> 1) : wid;
    int warp_n = (COUT == 128) ? (wid & 1) : 0;
    int base_tile = blockIdx.x * (ROWS / 16) + warp_m * 2;

    const uint4* AfH = (const uint4*)g_AfH;
    const uint4* AfL = (const uint4*)g_AfL;
    const uint2* WfH = (const uint2*)WfHp;
    const uint2* WfL = (const uint2*)WfLp;

    float c[2][8][4];
    #pragma unroll
    for (int mt = 0; mt < 2; mt++)
        #pragma unroll
        for (int nt = 0; nt < 8; nt++)
            #pragma unroll
            for (int i = 0; i < 4; i++) c[mt][nt][i] = 0.0f;

    #pragma unroll
    for (int ks = 0; ks < NKS; ks++) {
        uint4 Ah[2], Al[2];
        #pragma unroll
        for (int mt = 0; mt < 2; mt++) {
            size_t ai = ((size_t)(base_tile + mt) * NKS + ks) * 32 + lane;
            Ah[mt] = AfH[ai];
            Al[mt] = AfL[ai];
        }
        #pragma unroll
        for (int nt = 0; nt < 8; nt++) {
            int ct = warp_n * 8 + nt;
            size_t bi = ((size_t)ct * NKS + ks) * 32 + lane;
            uint2 Bh = WfH[bi];
            uint2 Bl = WfL[bi];
            #pragma unroll
            for (int mt = 0; mt < 2; mt++) {
                mma_bf16(c[mt][nt], (const unsigned*)&Ah[mt], (const unsigned*)&Bh);
                mma_bf16(c[mt][nt], (const unsigned*)&Ah[mt], (const unsigned*)&Bl);
                mma_bf16(c[mt][nt], (const unsigned*)&Al[mt], (const unsigned*)&Bh);
            }
        }
    }

    #pragma unroll
    for (int mt = 0; mt < 2; mt++) {
        int r0 = blockIdx.x * ROWS + warp_m * 32 + mt * 16 + g;
        #pragma unroll
        for (int nt = 0; nt < 8; nt++) {
            int col = (warp_n * 8 + nt) * 8 + 2 * t;
            if (r0 < nrows)
                *(__half2*)&H[(size_t)r0 * COUT + col] =
                    __floats2half2_rn(c[mt][nt][0], c[mt][nt][1]);
            if (r0 + 8 < nrows)
                *(__half2*)&H[(size_t)(r0 + 8) * COUT + col] =
                    __floats2half2_rn(c[mt][nt][2], c[mt][nt][3]);
        }
    }
}

// ---------------- agg1 (FUSE2), one pass, unroll-2 --------------------------
__global__ __launch_bounds__(512)
void node_aggregate_fuse2_kernel(const __half* __restrict__ h,
                                 const float* __restrict__ bias) {
    __shared__ unsigned sH[16][64], sL[16][64];
    int wid  = threadIdx.x >> 5;
    int lane = threadIdx.x & 31;
    int tile = blockIdx.x;                 // grid = REAL_TILES (exact)
    int n    = tile * 16 + wid;
    int beg  = g_rowptr[n];
    int end  = g_rowptr[n + 1];
    float ad = g_adst[n];

    float den = 0.0f;
    float a0 = 0.f, a1 = 0.f, a2 = 0.f, a3 = 0.f;
    int i = beg;
    for (; i + 2 <= end; i += 2) {
        int s0 = g_csr_src[i];
        int s1 = g_csr_src[i + 1];
        float l0 = g_asrc[s0] + ad;
        float l1 = g_asrc[s1] + ad;
        l0 = fmaxf(l0, NEG_SLOPE * l0);
        l1 = fmaxf(l1, NEG_SLOPE * l1);
        float e0 = __expf(l0);
        float e1 = __expf(l1);
        den += e0;
        den += e1;
        uint2 r0 = ((const uint2*)(h + (size_t)s0 * 128))[lane];
        uint2 r1 = ((const uint2*)(h + (size_t)s1 * 128))[lane];
        float2 f01 = __half22float2(*(const __half2*)&r0.x);
        float2 f23 = __half22float2(*(const __half2*)&r0.y);
        a0 += e0 * f01.x; a1 += e0 * f01.y;
        a2 += e0 * f23.x; a3 += e0 * f23.y;
        f01 = __half22float2(*(const __half2*)&r1.x);
        f23 = __half22float2(*(const __half2*)&r1.y);
        a0 += e1 * f01.x; a1 += e1 * f01.y;
        a2 += e1 * f23.x; a3 += e1 * f23.y;
    }
    if (i < end) {
        int s = g_csr_src[i];
        float l = g_asrc[s] + ad;
        l = fmaxf(l, NEG_SLOPE * l);
        float ev = __expf(l);
        den += ev;
        uint2 raw = ((const uint2*)(h + (size_t)s * 128))[lane];
        float2 f01 = __half22float2(*(const __half2*)&raw.x);
        float2 f23 = __half22float2(*(const __half2*)&raw.y);
        a0 += ev * f01.x; a1 += ev * f01.y;
        a2 += ev * f23.x; a3 += ev * f23.y;
    }

    float inv = 1.0f / (den + 1e-16f);
    float4 b = ((const float4*)bias)[lane];
    float4 r;
    r.x = fmaxf(a0 * inv + b.x, 0.f);
    r.y = fmaxf(a1 * inv + b.y, 0.f);
    r.z = fmaxf(a2 * inv + b.z, 0.f);
    r.w = fmaxf(a3 * inv + b.w, 0.f);

    // layer-2 attention dots
    float4 ps = ((const float4*)g_p2)[lane];
    float4 pd = ((const float4*)(g_p2 + 128))[lane];
    float s2 = r.x * ps.x + r.y * ps.y + r.z * ps.z + r.w * ps.w;
    float d2 = r.x * pd.x + r.y * pd.y + r.z * pd.z + r.w * pd.w;
    #pragma unroll
    for (int o = 16; o > 0; o >>= 1) {
        s2 += __shfl_xor_sync(0xffffffffu, s2, o);
        d2 += __shfl_xor_sync(0xffffffffu, d2, o);
    }
    if (lane == 0) {
        g_asrc2[n] = s2;
        g_adst2[n] = d2;
    }

    // stage packed words for sector-exact frag write
    unsigned hw, lw;
    pack_hl(r.x, r.y, hw, lw); sH[wid][2 * lane] = hw;     sL[wid][2 * lane] = lw;
    pack_hl(r.z, r.w, hw, lw); sH[wid][2 * lane + 1] = hw; sL[wid][2 * lane + 1] = lw;
    __syncthreads();

    int ks = lane >> 2, tt = lane & 3;
    if (wid < 8) {
        uint4 H4;
        H4.x = sH[wid][8 * ks + tt];     H4.y = sH[wid + 8][8 * ks + tt];
        H4.z = sH[wid][8 * ks + 4 + tt]; H4.w = sH[wid + 8][8 * ks + 4 + tt];
        ((uint4*)g_AfH)[((size_t)(tile * 8 + ks)) * 32 + 4 * wid + tt] = H4;
    } else {
        int w2 = wid - 8;
        uint4 L4;
        L4.x = sL[w2][8 * ks + tt];     L4.y = sL[w2 + 8][8 * ks + tt];
        L4.z = sL[w2][8 * ks + 4 + tt]; L4.w = sL[w2 + 8][8 * ks + 4 + tt];
        ((uint4*)g_AfL)[((size_t)(tile * 8 + ks)) * 32 + 4 * w2 + tt] = L4;
    }
}

// ---------------- agg2, one pass, unroll-2, writes final output --------------
template<int C>
__global__ void node_aggregate_kernel(const __half* __restrict__ h,
                                      const float* __restrict__ bias,
                                      float* __restrict__ out,
                                      const float* __restrict__ asrc,
                                      const float* __restrict__ adst) {
    int warp = (blockIdx.x * blockDim.x + threadIdx.x) >> 5;
    int lane = threadIdx.x & 31;
    if (warp >= N_NODES) return;
    int n   = warp;
    int beg = g_rowptr[n];
    int end = g_rowptr[n + 1];
    float ad = adst[n];

    float den = 0.0f;
    float a0 = 0.f, a1 = 0.f;
    int i = beg;
    for (; i + 2 <= end; i += 2) {
        int s0 = g_csr_src[i];
        int s1 = g_csr_src[i + 1];
        float l0 = asrc[s0] + ad;
        float l1 = asrc[s1] + ad;
        l0 = fmaxf(l0, NEG_SLOPE * l0);
        l1 = fmaxf(l1, NEG_SLOPE * l1);
        float e0 = __expf(l0);
        float e1 = __expf(l1);
        den += e0;
        den += e1;
        __half2 r0 = ((const __half2*)(h + (size_t)s0 * C))[lane];
        __half2 r1 = ((const __half2*)(h + (size_t)s1 * C))[lane];
        float2 f0 = __half22float2(r0);
        float2 f1 = __half22float2(r1);
        a0 += e0 * f0.x; a1 += e0 * f0.y;
        a0 += e1 * f1.x; a1 += e1 * f1.y;
    }
    if (i < end) {
        int s = g_csr_src[i];
        float l = asrc[s] + ad;
        l = fmaxf(l, NEG_SLOPE * l);
        float ev = __expf(l);
        den += ev;
        __half2 raw = ((const __half2*)(h + (size_t)s * C))[lane];
        float2 f = __half22float2(raw);
        a0 += ev * f.x; a1 += ev * f.y;
    }

    float inv = 1.0f / (den + 1e-16f);
    float2 b = ((const float2*)bias)[lane];
    float2 r;
    r.x = a0 * inv + b.x;
    r.y = a1 * inv + b.y;
    ((float2*)(out + (size_t)n * C))[lane] = r;
}

// ---------------- launch ----------------
extern "C" void kernel_launch(void* const* d_in, const int* in_sizes, int n_in,
                              void* d_out, int out_size) {
    const float* x   = (const float*)d_in[0];
    const int*   ei  = (const int*)d_in[1];
    const float* W1s = (const float*)d_in[2];
    const float* W1d = (const float*)d_in[3];
    const float* a1s = (const float*)d_in[4];
    const float* a1d = (const float*)d_in[5];
    const float* b1  = (const float*)d_in[6];
    const float* W2s = (const float*)d_in[7];
    const float* W2d = (const float*)d_in[8];
    const float* a2s = (const float*)d_in[9];
    const float* a2d = (const float*)d_in[10];
    const float* b2  = (const float*)d_in[11];
    float* out = (float*)d_out;

    const int* srcp = ei;
    const int* dstp = ei + N_EDGES;

    void *p_cnt, *p_h1, *p_h2, *p_WfH1, *p_WfL1, *p_WfH2, *p_WfL2;
    void *p_asrc2, *p_adst2;
    cudaGetSymbolAddress(&p_cnt, g_cnt);
    cudaGetSymbolAddress(&p_h1, g_h1);
    cudaGetSymbolAddress(&p_h2, g_h2);
    cudaGetSymbolAddress(&p_WfH1, g_WfH1);
    cudaGetSymbolAddress(&p_WfL1, g_WfL1);
    cudaGetSymbolAddress(&p_WfH2, g_WfH2);
    cudaGetSymbolAddress(&p_WfL2, g_WfL2);
    cudaGetSymbolAddress(&p_asrc2, g_asrc2);
    cudaGetSymbolAddress(&p_adst2, g_adst2);
    __half* h1 = (__half*)p_h1;
    __half* h2 = (__half*)p_h2;

    static cudaStream_t s_side = nullptr;
    static cudaEvent_t ev_fork = nullptr, ev_join = nullptr;
    if (!s_side) {
        cudaStreamCreateWithFlags(&s_side, cudaStreamNonBlocking);
        cudaEventCreateWithFlags(&ev_fork, cudaEventDisableTiming);
        cudaEventCreateWithFlags(&ev_join, cudaEventDisableTiming);
    }

    const int TB = 256;
    const int edgeBlocks = (N_EDGES + TB - 1) / TB;
    const int nodeBlocks = (N_NODES + TB - 1) / TB;
    const int nodeWarpBlocks = (N_NODES * 32 + TB - 1) / TB;

    // ---- fork event + side-stream memset ----
    cudaEventRecord(ev_fork, 0);
    cudaStreamWaitEvent(s_side, ev_fork, 0);
    cudaMemsetAsync(p_cnt, 0, N_NODES * sizeof(int), s_side);

    // ---- main chain ----
    prep_all_kernel<<<2 + DIM_HID / 8 + DIM_OUT / 8, 256>>>(                       // #1
        W1s, a1s, W1d, a1d, W2s, a2s, W2d, a2d);
    row_prep_kernel<<<PAD_TILES, 256>>>(x);                                        // #2
    gemm_frag_kernel<DIM_HID><<<(N_NODES + 127) / 128, 256>>>(                     // #3
        h1, N_NODES, (unsigned*)p_WfH1, (unsigned*)p_WfL1);

    // ---- CSR build on side stream (concurrent via fork event) ----
    hist_kernel<<<edgeBlocks, TB, 0, s_side>>>(dstp);                              // #4 <- ncu
    scan1_kernel<<<N_SCAN_BLOCKS, SCAN_BLK, 0, s_side>>>();
    scan2_kernel<<<1, 128, 0, s_side>>>();
    scan3_kernel<<<nodeBlocks, TB, 0, s_side>>>();
    scatter_kernel<<<edgeBlocks, TB, 0, s_side>>>(srcp, dstp);
    cudaEventRecord(ev_join, s_side);

    // ---- join: aggregate needs CSR + gemm1 ----
    cudaStreamWaitEvent(0, ev_join, 0);
    node_aggregate_fuse2_kernel<<<REAL_TILES, 512>>>(h1, b1);
    gemm_frag_kernel<DIM_OUT><<<(N_NODES + 255) / 256, 256>>>(h2, N_NODES,
                                                              (unsigned*)p_WfH2, (unsigned*)p_WfL2);
    node_aggregate_kernel<DIM_OUT><<<nodeWarpBlocks, TB>>>(
        h2, b2, out, (const float*)p_asrc2, (const float*)p_adst2);

    (void)in_sizes; (void)n_in; (void)out_size;
}

// round 15
// speedup vs baseline: 1.0103x; 1.0103x over previous
#include <cuda_runtime.h>
#include <cuda_fp16.h>
#include <cuda_bf16.h>
#include <math_constants.h>

// ---------------- problem constants ----------------
#define N_NODES 100000
#define N_EDGES 1600000
#define DIM_IN  128
#define DIM_HID 128
#define DIM_OUT 64
#define NEG_SLOPE 0.2f

#define KDIM 128
#define NKS  (KDIM / 16)              // 8 k-steps of 16
#define PAD_TILES 6256                // covers 782*8 (gemm1) and 391*16 (gemm2)
#define REAL_TILES (N_NODES / 16)     // 6250 exactly

#define SCAN_BLK 1024
#define N_SCAN_BLOCKS ((N_NODES + SCAN_BLK - 1) / SCAN_BLK)   // 98

// ---------------- scratch (device globals; no allocation allowed) ----------
__device__ __half g_h1[(size_t)N_NODES * DIM_HID];
__device__ __half g_h2[(size_t)N_NODES * DIM_OUT];
__device__ float  g_asrc[N_NODES],  g_adst[N_NODES];
__device__ float  g_asrc2[N_NODES], g_adst2[N_NODES];
__device__ float  g_p1[2 * 128];
__device__ float  g_p2[2 * 128];

__device__ unsigned g_AfH[(size_t)PAD_TILES * NKS * 32 * 4];
__device__ unsigned g_AfL[(size_t)PAD_TILES * NKS * 32 * 4];
__device__ unsigned g_WfH1[16 * NKS * 32 * 2], g_WfL1[16 * NKS * 32 * 2];
__device__ unsigned g_WfH2[8  * NKS * 32 * 2], g_WfL2[8  * NKS * 32 * 2];

// CSR scratch
__device__ int g_cnt[N_NODES];
__device__ int g_incl[N_NODES];
__device__ int g_bsum[N_SCAN_BLOCKS];
__device__ int g_boff[N_SCAN_BLOCKS];
__device__ int g_rowptr[N_NODES + 1];
__device__ int g_woff[N_NODES];
__device__ int g_csr_src[N_EDGES];

// ---------------- CSR build ----------------
__global__ void hist_kernel(const int* __restrict__ dst) {
    int e = blockIdx.x * blockDim.x + threadIdx.x;
    if (e >= N_EDGES) return;
    int d = dst[e];
    if ((unsigned)d < N_NODES) atomicAdd(&g_cnt[d], 1);
}

__global__ void scan1_kernel() {
    __shared__ int wsum[32];
    int tid  = threadIdx.x;
    int lane = tid & 31;
    int wid  = tid >> 5;
    int i = blockIdx.x * SCAN_BLK + tid;
    int x = (i < N_NODES) ? g_cnt[i] : 0;
    #pragma unroll
    for (int off = 1; off < 32; off <<= 1) {
        int y = __shfl_up_sync(0xffffffffu, x, off);
        if (lane >= off) x += y;
    }
    if (lane == 31) wsum[wid] = x;
    __syncthreads();
    if (wid == 0) {
        int y = wsum[lane];
        #pragma unroll
        for (int off = 1; off < 32; off <<= 1) {
            int z = __shfl_up_sync(0xffffffffu, y, off);
            if (lane >= off) y += z;
        }
        wsum[lane] = y;
    }
    __syncthreads();
    if (wid > 0) x += wsum[wid - 1];
    if (i < N_NODES) g_incl[i] = x;
    if (tid == SCAN_BLK - 1) g_bsum[blockIdx.x] = x;
}

__global__ void scan2_kernel() {
    __shared__ int s[128];
    int tid = threadIdx.x;
    int v0 = (tid < N_SCAN_BLOCKS) ? g_bsum[tid] : 0;
    s[tid] = v0;
    __syncthreads();
    #pragma unroll
    for (int off = 1; off < 128; off <<= 1) {
        int v = (tid >= off) ? s[tid - off] : 0;
        __syncthreads();
        s[tid] += v;
        __syncthreads();
    }
    if (tid < N_SCAN_BLOCKS) g_boff[tid] = s[tid] - v0;
}

__global__ void scan3_kernel() {
    int i = blockIdx.x * blockDim.x + threadIdx.x;
    if (i >= N_NODES) return;
    int excl = g_incl[i] - g_cnt[i] + g_boff[i / SCAN_BLK];
    g_rowptr[i] = excl;
    g_woff[i]   = excl;
    if (i == 0) g_rowptr[N_NODES] = N_EDGES;
}

__global__ void scatter_kernel(const int* __restrict__ src, const int* __restrict__ dst) {
    int e = blockIdx.x * blockDim.x + threadIdx.x;
    if (e >= N_EDGES) return;
    int s = src[e];
    int d = dst[e];
    if ((unsigned)s >= N_NODES || (unsigned)d >= N_NODES) return;
    int pos = atomicAdd(&g_woff[d], 1);
    g_csr_src[pos] = s;
}

// ---------------- bf16 split / pack helpers ----------------
__device__ __forceinline__ void split_bf16(float x, __nv_bfloat16& h, __nv_bfloat16& l) {
    h = __float2bfloat16_rn(x);
    l = __float2bfloat16_rn(x - __bfloat162float(h));
}
__device__ __forceinline__ unsigned pack_bf16(__nv_bfloat16 a, __nv_bfloat16 b) {
    __nv_bfloat162 t;
    t.x = a; t.y = b;
    return *(unsigned*)&t;
}
__device__ __forceinline__ void pack_hl(float x, float y, unsigned& hw, unsigned& lw) {
    __nv_bfloat16 hx, lx, hy, ly;
    split_bf16(x, hx, lx);
    split_bf16(y, hy, ly);
    hw = pack_bf16(hx, hy);
    lw = pack_bf16(lx, ly);
}

// ---------------- merged prep: p1, p2, W1 frags, W2 frags in one launch -----
__device__ __forceinline__ void convertW_body(const float* __restrict__ W, int COUT, int ct,
                                              unsigned* __restrict__ WfH,
                                              unsigned* __restrict__ WfL) {
    int ks   = threadIdx.x >> 5;
    int lane = threadIdx.x & 31;
    int g = lane >> 2, t = lane & 3;
    size_t base = (((size_t)ct * NKS + ks) * 32 + lane) * 2;
    #pragma unroll
    for (int r = 0; r < 2; r++) {
        int k   = ks * 16 + 2 * t + r * 8;
        int col = ct * 8 + g;
        float e0 = W[(size_t)k * COUT + col];
        float e1 = W[(size_t)(k + 1) * COUT + col];
        __nv_bfloat16 h0, l0, h1, l1;
        split_bf16(e0, h0, l0);
        split_bf16(e1, h1, l1);
        WfH[base + r] = pack_bf16(h0, h1);
        WfL[base + r] = pack_bf16(l0, l1);
    }
}

__global__ void prep_all_kernel(const float* __restrict__ W1s, const float* __restrict__ a1s,
                                const float* __restrict__ W1d, const float* __restrict__ a1d,
                                const float* __restrict__ W2s, const float* __restrict__ a2s,
                                const float* __restrict__ W2d, const float* __restrict__ a2d) {
    int b = blockIdx.x;
    if (b == 0) {
        if (threadIdx.x >= 128) return;
        int i = threadIdx.x;
        float s = 0.f, d = 0.f;
        for (int c = 0; c < DIM_HID; c++) {
            s += W1s[i * DIM_HID + c] * a1s[c];
            d += W1d[i * DIM_HID + c] * a1d[c];
        }
        g_p1[i] = s;
        g_p1[128 + i] = d;
    } else if (b == 1) {
        if (threadIdx.x >= 128) return;
        int i = threadIdx.x;
        float s = 0.f, d = 0.f;
        for (int c = 0; c < DIM_OUT; c++) {
            s += W2s[i * DIM_OUT + c] * a2s[c];
            d += W2d[i * DIM_OUT + c] * a2d[c];
        }
        g_p2[i] = s;
        g_p2[128 + i] = d;
    } else if (b < 2 + DIM_HID / 8) {
        convertW_body(W1s, DIM_HID, b - 2, g_WfH1, g_WfL1);
    } else {
        convertW_body(W2s, DIM_OUT, b - 2 - DIM_HID / 8, g_WfH2, g_WfL2);
    }
}

// ---------------- row_prep: tile per block, warp owns row-pair (w, w+8) ----
__global__ __launch_bounds__(256)
void row_prep_kernel(const float* __restrict__ feat) {
    __shared__ unsigned sH[8][2][64];
    __shared__ unsigned sL[8][2][64];
    int tile = blockIdx.x;
    int wid  = threadIdx.x >> 5;
    int lane = threadIdx.x & 31;

    float4 ps = ((const float4*)g_p1)[lane];
    float4 pd = ((const float4*)(g_p1 + 128))[lane];
    int r0 = tile * 16 + wid;
    int r1 = r0 + 8;
    float4 v0 = make_float4(0.f, 0.f, 0.f, 0.f);
    float4 v1 = make_float4(0.f, 0.f, 0.f, 0.f);
    if (r0 < N_NODES) v0 = ((const float4*)(feat + (size_t)r0 * 128))[lane];
    if (r1 < N_NODES) v1 = ((const float4*)(feat + (size_t)r1 * 128))[lane];

    float s0 = v0.x * ps.x + v0.y * ps.y + v0.z * ps.z + v0.w * ps.w;
    float d0 = v0.x * pd.x + v0.y * pd.y + v0.z * pd.z + v0.w * pd.w;
    float s1 = v1.x * ps.x + v1.y * ps.y + v1.z * ps.z + v1.w * ps.w;
    float d1 = v1.x * pd.x + v1.y * pd.y + v1.z * pd.z + v1.w * pd.w;
    #pragma unroll
    for (int o = 16; o > 0; o >>= 1) {
        s0 += __shfl_xor_sync(0xffffffffu, s0, o);
        d0 += __shfl_xor_sync(0xffffffffu, d0, o);
        s1 += __shfl_xor_sync(0xffffffffu, s1, o);
        d1 += __shfl_xor_sync(0xffffffffu, d1, o);
    }
    if (lane == 0) {
        if (r0 < N_NODES) { g_asrc[r0] = s0; g_adst[r0] = d0; }
        if (r1 < N_NODES) { g_asrc[r1] = s1; g_adst[r1] = d1; }
    }

    unsigned hw, lw;
    pack_hl(v0.x, v0.y, hw, lw); sH[wid][0][2 * lane] = hw;     sL[wid][0][2 * lane] = lw;
    pack_hl(v0.z, v0.w, hw, lw); sH[wid][0][2 * lane + 1] = hw; sL[wid][0][2 * lane + 1] = lw;
    pack_hl(v1.x, v1.y, hw, lw); sH[wid][1][2 * lane] = hw;     sL[wid][1][2 * lane] = lw;
    pack_hl(v1.z, v1.w, hw, lw); sH[wid][1][2 * lane + 1] = hw; sL[wid][1][2 * lane + 1] = lw;
    __syncwarp();

    int ks = lane >> 2, tt = lane & 3;
    uint4 H4, L4;
    H4.x = sH[wid][0][8 * ks + tt];     H4.y = sH[wid][1][8 * ks + tt];
    H4.z = sH[wid][0][8 * ks + 4 + tt]; H4.w = sH[wid][1][8 * ks + 4 + tt];
    L4.x = sL[wid][0][8 * ks + tt];     L4.y = sL[wid][1][8 * ks + tt];
    L4.z = sL[wid][0][8 * ks + 4 + tt]; L4.w = sL[wid][1][8 * ks + 4 + tt];
    size_t a = ((size_t)(tile * 8 + ks)) * 32 + 4 * wid + tt;
    ((uint4*)g_AfH)[a] = H4;
    ((uint4*)g_AfL)[a] = L4;
}

// ---------------- bf16 3x mma GEMM (uint4 A frags) --------------
__device__ __forceinline__ void mma_bf16(float c[4], const unsigned a[4], const unsigned b[2]) {
    asm volatile(
        "mma.sync.aligned.m16n8k16.row.col.f32.bf16.bf16.f32 "
        "{%0,%1,%2,%3}, {%4,%5,%6,%7}, {%8,%9}, {%0,%1,%2,%3};"
        : "+f"(c[0]), "+f"(c[1]), "+f"(c[2]), "+f"(c[3])
        : "r"(a[0]), "r"(a[1]), "r"(a[2]), "r"(a[3]), "r"(b[0]), "r"(b[1]));
}

template<int COUT>
__global__ __launch_bounds__(256, 2)
void gemm_frag_kernel(__half* __restrict__ H, int nrows,
                      const unsigned* __restrict__ WfHp, const unsigned* __restrict__ WfLp) {
    constexpr int WN = (COUT == 128) ? 2 : 1;
    constexpr int WMCNT = 8 / WN;
    constexpr int ROWS = WMCNT * 32;

    int wid  = threadIdx.x >> 5;
    int lane = threadIdx.x & 31;
    int g = lane >> 2, t = lane & 3;
    int warp_m = (COUT == 128) ? (wid >> 1) : wid;
    int warp_n = (COUT == 128) ? (wid & 1) : 0;
    int base_tile = blockIdx.x * (ROWS / 16) + warp_m * 2;

    const uint4* AfH = (const uint4*)g_AfH;
    const uint4* AfL = (const uint4*)g_AfL;
    const uint2* WfH = (const uint2*)WfHp;
    const uint2* WfL = (const uint2*)WfLp;

    float c[2][8][4];
    #pragma unroll
    for (int mt = 0; mt < 2; mt++)
        #pragma unroll
        for (int nt = 0; nt < 8; nt++)
            #pragma unroll
            for (int i = 0; i < 4; i++) c[mt][nt][i] = 0.0f;

    #pragma unroll
    for (int ks = 0; ks < NKS; ks++) {
        uint4 Ah[2], Al[2];
        #pragma unroll
        for (int mt = 0; mt < 2; mt++) {
            size_t ai = ((size_t)(base_tile + mt) * NKS + ks) * 32 + lane;
            Ah[mt] = AfH[ai];
            Al[mt] = AfL[ai];
        }
        #pragma unroll
        for (int nt = 0; nt < 8; nt++) {
            int ct = warp_n * 8 + nt;
            size_t bi = ((size_t)ct * NKS + ks) * 32 + lane;
            uint2 Bh = WfH[bi];
            uint2 Bl = WfL[bi];
            #pragma unroll
            for (int mt = 0; mt < 2; mt++) {
                mma_bf16(c[mt][nt], (const unsigned*)&Ah[mt], (const unsigned*)&Bh);
                mma_bf16(c[mt][nt], (const unsigned*)&Ah[mt], (const unsigned*)&Bl);
                mma_bf16(c[mt][nt], (const unsigned*)&Al[mt], (const unsigned*)&Bh);
            }
        }
    }

    #pragma unroll
    for (int mt = 0; mt < 2; mt++) {
        int r0 = blockIdx.x * ROWS + warp_m * 32 + mt * 16 + g;
        #pragma unroll
        for (int nt = 0; nt < 8; nt++) {
            int col = (warp_n * 8 + nt) * 8 + 2 * t;
            if (r0 < nrows)
                *(__half2*)&H[(size_t)r0 * COUT + col] =
                    __floats2half2_rn(c[mt][nt][0], c[mt][nt][1]);
            if (r0 + 8 < nrows)
                *(__half2*)&H[(size_t)(r0 + 8) * COUT + col] =
                    __floats2half2_rn(c[mt][nt][2], c[mt][nt][3]);
        }
    }
}

// ---------------- agg1 (FUSE2), one pass, index-pipelined --------------------
__global__ __launch_bounds__(512)
void node_aggregate_fuse2_kernel(const __half* __restrict__ h,
                                 const float* __restrict__ bias) {
    __shared__ unsigned sH[16][64], sL[16][64];
    int wid  = threadIdx.x >> 5;
    int lane = threadIdx.x & 31;
    int tile = blockIdx.x;                 // grid = REAL_TILES (exact)
    int n    = tile * 16 + wid;
    int beg  = g_rowptr[n];
    int end  = g_rowptr[n + 1];
    float ad = g_adst[n];

    float den = 0.0f;
    float a0 = 0.f, a1 = 0.f, a2 = 0.f, a3 = 0.f;

    // software pipeline: indices loaded one iteration ahead
    int i = beg;
    int sA = (i < end) ? g_csr_src[i] : 0;
    int sB = (i + 1 < end) ? g_csr_src[i + 1] : 0;
    for (; i + 2 <= end; i += 2) {
        int j = i + 2;
        int sC = (j < end) ? g_csr_src[j] : 0;
        int sD = (j + 1 < end) ? g_csr_src[j + 1] : 0;
        float lA = g_asrc[sA] + ad;                    // gathers use prefetched idx
        float lB = g_asrc[sB] + ad;
        uint2 rA = ((const uint2*)(h + (size_t)sA * 128))[lane];
        uint2 rB = ((const uint2*)(h + (size_t)sB * 128))[lane];
        lA = fmaxf(lA, NEG_SLOPE * lA);
        lB = fmaxf(lB, NEG_SLOPE * lB);
        float eA = __expf(lA);
        float eB = __expf(lB);
        den += eA;
        den += eB;
        float2 f01 = __half22float2(*(const __half2*)&rA.x);
        float2 f23 = __half22float2(*(const __half2*)&rA.y);
        a0 += eA * f01.x; a1 += eA * f01.y;
        a2 += eA * f23.x; a3 += eA * f23.y;
        f01 = __half22float2(*(const __half2*)&rB.x);
        f23 = __half22float2(*(const __half2*)&rB.y);
        a0 += eB * f01.x; a1 += eB * f01.y;
        a2 += eB * f23.x; a3 += eB * f23.y;
        sA = sC;
        sB = sD;
    }
    if (i < end) {                                     // at most one edge left; sA == csr[i]
        float l = g_asrc[sA] + ad;
        l = fmaxf(l, NEG_SLOPE * l);
        float ev = __expf(l);
        den += ev;
        uint2 raw = ((const uint2*)(h + (size_t)sA * 128))[lane];
        float2 f01 = __half22float2(*(const __half2*)&raw.x);
        float2 f23 = __half22float2(*(const __half2*)&raw.y);
        a0 += ev * f01.x; a1 += ev * f01.y;
        a2 += ev * f23.x; a3 += ev * f23.y;
    }

    float inv = 1.0f / (den + 1e-16f);
    float4 b = ((const float4*)bias)[lane];
    float4 r;
    r.x = fmaxf(a0 * inv + b.x, 0.f);
    r.y = fmaxf(a1 * inv + b.y, 0.f);
    r.z = fmaxf(a2 * inv + b.z, 0.f);
    r.w = fmaxf(a3 * inv + b.w, 0.f);

    // layer-2 attention dots
    float4 ps = ((const float4*)g_p2)[lane];
    float4 pd = ((const float4*)(g_p2 + 128))[lane];
    float s2 = r.x * ps.x + r.y * ps.y + r.z * ps.z + r.w * ps.w;
    float d2 = r.x * pd.x + r.y * pd.y + r.z * pd.z + r.w * pd.w;
    #pragma unroll
    for (int o = 16; o > 0; o >>= 1) {
        s2 += __shfl_xor_sync(0xffffffffu, s2, o);
        d2 += __shfl_xor_sync(0xffffffffu, d2, o);
    }
    if (lane == 0) {
        g_asrc2[n] = s2;
        g_adst2[n] = d2;
    }

    // stage packed words for sector-exact frag write
    unsigned hw, lw;
    pack_hl(r.x, r.y, hw, lw); sH[wid][2 * lane] = hw;     sL[wid][2 * lane] = lw;
    pack_hl(r.z, r.w, hw, lw); sH[wid][2 * lane + 1] = hw; sL[wid][2 * lane + 1] = lw;
    __syncthreads();

    int ks = lane >> 2, tt = lane & 3;
    if (wid < 8) {
        uint4 H4;
        H4.x = sH[wid][8 * ks + tt];     H4.y = sH[wid + 8][8 * ks + tt];
        H4.z = sH[wid][8 * ks + 4 + tt]; H4.w = sH[wid + 8][8 * ks + 4 + tt];
        ((uint4*)g_AfH)[((size_t)(tile * 8 + ks)) * 32 + 4 * wid + tt] = H4;
    } else {
        int w2 = wid - 8;
        uint4 L4;
        L4.x = sL[w2][8 * ks + tt];     L4.y = sL[w2 + 8][8 * ks + tt];
        L4.z = sL[w2][8 * ks + 4 + tt]; L4.w = sL[w2 + 8][8 * ks + 4 + tt];
        ((uint4*)g_AfL)[((size_t)(tile * 8 + ks)) * 32 + 4 * w2 + tt] = L4;
    }
}

// ---------------- agg2, one pass, index-pipelined, writes final output -------
template<int C>
__global__ void node_aggregate_kernel(const __half* __restrict__ h,
                                      const float* __restrict__ bias,
                                      float* __restrict__ out,
                                      const float* __restrict__ asrc,
                                      const float* __restrict__ adst) {
    int warp = (blockIdx.x * blockDim.x + threadIdx.x) >> 5;
    int lane = threadIdx.x & 31;
    if (warp >= N_NODES) return;
    int n   = warp;
    int beg = g_rowptr[n];
    int end = g_rowptr[n + 1];
    float ad = adst[n];

    float den = 0.0f;
    float a0 = 0.f, a1 = 0.f;
    int i = beg;
    int sA = (i < end) ? g_csr_src[i] : 0;
    int sB = (i + 1 < end) ? g_csr_src[i + 1] : 0;
    for (; i + 2 <= end; i += 2) {
        int j = i + 2;
        int sC = (j < end) ? g_csr_src[j] : 0;
        int sD = (j + 1 < end) ? g_csr_src[j + 1] : 0;
        float lA = asrc[sA] + ad;
        float lB = asrc[sB] + ad;
        __half2 rA = ((const __half2*)(h + (size_t)sA * C))[lane];
        __half2 rB = ((const __half2*)(h + (size_t)sB * C))[lane];
        lA = fmaxf(lA, NEG_SLOPE * lA);
        lB = fmaxf(lB, NEG_SLOPE * lB);
        float eA = __expf(lA);
        float eB = __expf(lB);
        den += eA;
        den += eB;
        float2 f0 = __half22float2(rA);
        float2 f1 = __half22float2(rB);
        a0 += eA * f0.x; a1 += eA * f0.y;
        a0 += eB * f1.x; a1 += eB * f1.y;
        sA = sC;
        sB = sD;
    }
    if (i < end) {
        float l = asrc[sA] + ad;
        l = fmaxf(l, NEG_SLOPE * l);
        float ev = __expf(l);
        den += ev;
        __half2 raw = ((const __half2*)(h + (size_t)sA * C))[lane];
        float2 f = __half22float2(raw);
        a0 += ev * f.x; a1 += ev * f.y;
    }

    float inv = 1.0f / (den + 1e-16f);
    float2 b = ((const float2*)bias)[lane];
    float2 r;
    r.x = a0 * inv + b.x;
    r.y = a1 * inv + b.y;
    ((float2*)(out + (size_t)n * C))[lane] = r;
}

// ---------------- launch ----------------
extern "C" void kernel_launch(void* const* d_in, const int* in_sizes, int n_in,
                              void* d_out, int out_size) {
    const float* x   = (const float*)d_in[0];
    const int*   ei  = (const int*)d_in[1];
    const float* W1s = (const float*)d_in[2];
    const float* W1d = (const float*)d_in[3];
    const float* a1s = (const float*)d_in[4];
    const float* a1d = (const float*)d_in[5];
    const float* b1  = (const float*)d_in[6];
    const float* W2s = (const float*)d_in[7];
    const float* W2d = (const float*)d_in[8];
    const float* a2s = (const float*)d_in[9];
    const float* a2d = (const float*)d_in[10];
    const float* b2  = (const float*)d_in[11];
    float* out = (float*)d_out;

    const int* srcp = ei;
    const int* dstp = ei + N_EDGES;

    void *p_cnt, *p_h1, *p_h2, *p_WfH1, *p_WfL1, *p_WfH2, *p_WfL2;
    void *p_asrc2, *p_adst2;
    cudaGetSymbolAddress(&p_cnt, g_cnt);
    cudaGetSymbolAddress(&p_h1, g_h1);
    cudaGetSymbolAddress(&p_h2, g_h2);
    cudaGetSymbolAddress(&p_WfH1, g_WfH1);
    cudaGetSymbolAddress(&p_WfL1, g_WfL1);
    cudaGetSymbolAddress(&p_WfH2, g_WfH2);
    cudaGetSymbolAddress(&p_WfL2, g_WfL2);
    cudaGetSymbolAddress(&p_asrc2, g_asrc2);
    cudaGetSymbolAddress(&p_adst2, g_adst2);
    __half* h1 = (__half*)p_h1;
    __half* h2 = (__half*)p_h2;

    static cudaStream_t s_side = nullptr;
    static cudaEvent_t ev_fork = nullptr, ev_join = nullptr;
    if (!s_side) {
        cudaStreamCreateWithFlags(&s_side, cudaStreamNonBlocking);
        cudaEventCreateWithFlags(&ev_fork, cudaEventDisableTiming);
        cudaEventCreateWithFlags(&ev_join, cudaEventDisableTiming);
    }

    const int TB = 256;
    const int edgeBlocks = (N_EDGES + TB - 1) / TB;
    const int nodeBlocks = (N_NODES + TB - 1) / TB;
    const int nodeWarpBlocks = (N_NODES * 32 + TB - 1) / TB;

    // ---- fork event + side-stream memset ----
    cudaEventRecord(ev_fork, 0);
    cudaStreamWaitEvent(s_side, ev_fork, 0);
    cudaMemsetAsync(p_cnt, 0, N_NODES * sizeof(int), s_side);

    // ---- main chain ----
    prep_all_kernel<<<2 + DIM_HID / 8 + DIM_OUT / 8, 256>>>(                       // #1
        W1s, a1s, W1d, a1d, W2s, a2s, W2d, a2d);
    row_prep_kernel<<<PAD_TILES, 256>>>(x);                                        // #2
    gemm_frag_kernel<DIM_HID><<<(N_NODES + 127) / 128, 256>>>(                     // #3
        h1, N_NODES, (unsigned*)p_WfH1, (unsigned*)p_WfL1);

    // ---- CSR build on side stream (concurrent via fork event) ----
    hist_kernel<<<edgeBlocks, TB, 0, s_side>>>(dstp);                              // #4 <- ncu
    scan1_kernel<<<N_SCAN_BLOCKS, SCAN_BLK, 0, s_side>>>();
    scan2_kernel<<<1, 128, 0, s_side>>>();
    scan3_kernel<<<nodeBlocks, TB, 0, s_side>>>();
    scatter_kernel<<<edgeBlocks, TB, 0, s_side>>>(srcp, dstp);
    cudaEventRecord(ev_join, s_side);

    // ---- join: aggregate needs CSR + gemm1 ----
    cudaStreamWaitEvent(0, ev_join, 0);
    node_aggregate_fuse2_kernel<<<REAL_TILES, 512>>>(h1, b1);
    gemm_frag_kernel<DIM_OUT><<<(N_NODES + 255) / 256, 256>>>(h2, N_NODES,
                                                              (unsigned*)p_WfH2, (unsigned*)p_WfL2);
    node_aggregate_kernel<DIM_OUT><<<nodeWarpBlocks, TB>>>(
        h2, b2, out, (const float*)p_asrc2, (const float*)p_adst2);

    (void)in_sizes; (void)n_in; (void)out_size;
}